// round 4
// baseline (speedup 1.0000x reference)
#include <cuda_runtime.h>
#include <stdint.h>

#define IN_SIZE  4096
#define OUT_SIZE 4096
#define BATCH    256

#define BK      32
#define NSTAGE  (IN_SIZE / BK)     // 128
#define STAGES  4
#define STAGE_BYTES 24576          // A: 8KB + B: 16KB
#define SMEM_BYTES (STAGES * STAGE_BYTES)

// Transposed dense weight g_Wt[out][in]; fp32 during scatter, tf32 bits after cvt pass.
__device__ float    g_Wt[(size_t)IN_SIZE * OUT_SIZE];
__device__ uint32_t g_Xt[(size_t)BATCH * IN_SIZE];     // X as tf32 bit patterns
__device__ int      g_idx_is64;

// ---------------------------------------------------------------------------
// helpers
// ---------------------------------------------------------------------------
__device__ __forceinline__ uint32_t f2tf32(float f) {
    uint32_t u;
    asm("cvt.rna.tf32.f32 %0, %1;" : "=r"(u) : "f"(f));
    return u;
}
__device__ __forceinline__ uint32_t smem_u32(const void* p) {
    uint32_t a;
    asm("{ .reg .u64 t; cvta.to.shared.u64 t, %1; cvt.u32.u64 %0, t; }"
        : "=r"(a) : "l"(p));
    return a;
}
__device__ __forceinline__ void cpa16(uint32_t s, const void* g) {
    asm volatile("cp.async.cg.shared.global [%0], [%1], 16;" :: "r"(s), "l"(g));
}
__device__ __forceinline__ void cpa_commit() {
    asm volatile("cp.async.commit_group;" ::: "memory");
}
template <int N>
__device__ __forceinline__ void cpa_wait() {
    asm volatile("cp.async.wait_group %0;" :: "n"(N) : "memory");
}
__device__ __forceinline__ void mma_tf32(float& d0, float& d1, float& d2, float& d3,
                                         uint32_t a0, uint32_t a1, uint32_t a2, uint32_t a3,
                                         uint32_t b0, uint32_t b1) {
    asm volatile(
        "mma.sync.aligned.m16n8k8.row.col.f32.tf32.tf32.f32 "
        "{%0,%1,%2,%3}, {%4,%5,%6,%7}, {%8,%9}, {%0,%1,%2,%3};"
        : "+f"(d0), "+f"(d1), "+f"(d2), "+f"(d3)
        : "r"(a0), "r"(a1), "r"(a2), "r"(a3), "r"(b0), "r"(b1));
}

// ---------------------------------------------------------------------------
// Zero Wt
// ---------------------------------------------------------------------------
__global__ void zero_w_kernel() {
    size_t i = (size_t)blockIdx.x * blockDim.x + threadIdx.x;
    reinterpret_cast<float4*>(g_Wt)[i] = make_float4(0.f, 0.f, 0.f, 0.f);
}

// ---------------------------------------------------------------------------
// Detect idx dtype: indices < 4096 => int64 layout has all odd u32 words zero.
// ---------------------------------------------------------------------------
__global__ void detect_idx_kernel(const uint32_t* __restrict__ idx_words) {
    if (threadIdx.x == 0) {
        uint32_t acc = 0;
#pragma unroll
        for (int i = 0; i < 64; ++i) acc |= idx_words[2 * i + 1];
        g_idx_is64 = (acc == 0u) ? 1 : 0;
    }
}

// ---------------------------------------------------------------------------
// Scatter: g_Wt[col][row] += val (duplicates accumulate; fp32 atomics)
// ---------------------------------------------------------------------------
__global__ void scatter_kernel(const void* __restrict__ idx,
                               const float* __restrict__ val,
                               int nnz) {
    int i = blockIdx.x * blockDim.x + threadIdx.x;
    if (i >= nnz) return;
    int row, col;
    if (g_idx_is64) {
        longlong2 p = reinterpret_cast<const longlong2*>(idx)[i];
        row = (int)p.x;
        col = (int)p.y;
    } else {
        int2 p = reinterpret_cast<const int2*>(idx)[i];
        row = p.x;
        col = p.y;
    }
    atomicAdd(&g_Wt[(size_t)col * IN_SIZE + row], val[i]);
}

// ---------------------------------------------------------------------------
// In-place W fp32 -> tf32(RNA) bit conversion; X -> g_Xt
// ---------------------------------------------------------------------------
__global__ void cvt_w_kernel() {
    size_t i = (size_t)blockIdx.x * blockDim.x + threadIdx.x;
    float4 v = reinterpret_cast<const float4*>(g_Wt)[i];
    uint4 u = make_uint4(f2tf32(v.x), f2tf32(v.y), f2tf32(v.z), f2tf32(v.w));
    reinterpret_cast<uint4*>(g_Wt)[i] = u;
}
__global__ void cvt_x_kernel(const float* __restrict__ X) {
    size_t i = (size_t)blockIdx.x * blockDim.x + threadIdx.x;
    float4 v = reinterpret_cast<const float4*>(X)[i];
    uint4 u = make_uint4(f2tf32(v.x), f2tf32(v.y), f2tf32(v.z), f2tf32(v.w));
    reinterpret_cast<uint4*>(g_Xt)[i] = u;
}

// ---------------------------------------------------------------------------
// tf32 mma.sync GEMM v2: out[256,4096] = relu(X @ W + bias), W = g_Wt^T.
//
// CTA tile 64(M) x 128(N); grid (32, 4) = 128 CTAs (one wave on 148 SMs).
// 8 warps as 2(m) x 4(n); warp tile 32x32.
// K staged 32 per iteration, 4-stage cp.async pipeline, prefetch distance 3.
//
// Fragment-permuted SMEM layout (per stage; A 8KB then B 16KB):
//   A word = ksub*512  + (m>>4)*128 + vi*32 + pos   vi=((m&15)>>3)|((c>>2)<<1)
//   B word = ksub*1024 + (n>>3)*64  + vi*32 + pos   vi=c>>2
//   pos = lane ^ (g<<2),  lane=(r&7 or n&7)*4+(c&3),  g = ksub*2 + (c>>2)
// Every 16B global chunk (fixed row, 4 consecutive k, k%4==0) maps to one
// 16B-aligned smem quad (XOR touches bits>=2 only) -> cp.async 16B works.
// ---------------------------------------------------------------------------
__global__ __launch_bounds__(256, 1)
void gemm_tf32_mma(const float* __restrict__ bias, float* __restrict__ out) {
    extern __shared__ uint32_t smu[];
    const uint32_t sbase0 = smem_u32(smu);

    const int tid   = threadIdx.x;
    const int lane  = tid & 31;
    const int wid   = tid >> 5;
    const int warpm = wid & 1;          // 0..1 -> 32 rows each
    const int warpn = wid >> 1;         // 0..3 -> 32 cols each
    const int m0 = blockIdx.y * 64;
    const int n0 = blockIdx.x * 128;

    // staging map: thread t handles quad sj of rows {srow, srow+32} (A) and
    // rows {srow+32i, i=0..3} (B)
    const int srow = tid >> 3;          // 0..31
    const int sj   = tid & 7;           // k-quad index in the 32-wide stage

    const uint32_t* Ag = g_Xt + (size_t)(m0 + srow) * IN_SIZE + sj * 4;
    const uint32_t* Bg = reinterpret_cast<const uint32_t*>(g_Wt) +
                         (size_t)(n0 + srow) * IN_SIZE + sj * 4;

    // byte offsets within a stage region
    uint32_t offA[2], offB[4];
#pragma unroll
    for (int i = 0; i < 2; ++i) {
        int m = srow + 32 * i;
        offA[i] = 4u * ((uint32_t)(sj >> 1) * 512 + (uint32_t)(m >> 4) * 128 +
                        ((((uint32_t)(m & 15) >> 3) | ((uint32_t)(sj & 1) << 1)) * 32) +
                        ((((uint32_t)(m & 7) * 4)) ^ ((uint32_t)sj << 2)));
    }
#pragma unroll
    for (int i = 0; i < 4; ++i) {
        int n = srow + 32 * i;
        offB[i] = 8192u + 4u * ((uint32_t)(sj >> 1) * 1024 + (uint32_t)(n >> 3) * 64 +
                                ((uint32_t)(sj & 1) * 32) +
                                ((((uint32_t)(n & 7) * 4)) ^ ((uint32_t)sj << 2)));
    }

    float acc[2][4][4];
#pragma unroll
    for (int a = 0; a < 2; ++a)
#pragma unroll
        for (int b = 0; b < 4; ++b)
#pragma unroll
            for (int d = 0; d < 4; ++d) acc[a][b][d] = 0.f;

    // ---- prologue: issue stages 0..2
#pragma unroll
    for (int ps = 0; ps < 3; ++ps) {
        const uint32_t sb = sbase0 + (uint32_t)ps * STAGE_BYTES;
#pragma unroll
        for (int i = 0; i < 2; ++i)
            cpa16(sb + offA[i], Ag + (size_t)(32 * i) * IN_SIZE + ps * BK);
#pragma unroll
        for (int i = 0; i < 4; ++i)
            cpa16(sb + offB[i], Bg + (size_t)(32 * i) * IN_SIZE + ps * BK);
        cpa_commit();
    }

    const uint32_t abase = (uint32_t)(warpm * 2) * 512;  // A msub group offset (bytes)
    const uint32_t bbase = (uint32_t)(warpn * 4) * 256;  // B nsub group offset (bytes)

    for (int s = 0; s < NSTAGE; ++s) {
        cpa_wait<2>();
        __syncthreads();

        const uint32_t sb = sbase0 + (uint32_t)(s & 3) * STAGE_BYTES;
        const uint32_t* As = (const uint32_t*)(uintptr_t)0;  // unused; computed via asm addressing below
        (void)As;

#pragma unroll
        for (int ks = 0; ks < 4; ++ks) {
            uint32_t afrag[2][4];
#pragma unroll
            for (int msub = 0; msub < 2; ++msub)
#pragma unroll
                for (int vi = 0; vi < 4; ++vi) {
                    const int g = ks * 2 + (vi >> 1);
                    const uint32_t addr = sb + 4u * ((uint32_t)(ks * 512) +
                                         (abase >> 2) + (uint32_t)(msub * 128) +
                                         (uint32_t)(vi * 32) +
                                         (uint32_t)(lane ^ (g << 2)));
                    asm volatile("ld.shared.b32 %0, [%1];"
                                 : "=r"(afrag[msub][vi]) : "r"(addr));
                }
            uint32_t bfrag[4][2];
#pragma unroll
            for (int nsub = 0; nsub < 4; ++nsub)
#pragma unroll
                for (int vi = 0; vi < 2; ++vi) {
                    const int g = ks * 2 + vi;
                    const uint32_t addr = sb + 8192u + 4u * ((uint32_t)(ks * 1024) +
                                         (bbase >> 2) + (uint32_t)(nsub * 64) +
                                         (uint32_t)(vi * 32) +
                                         (uint32_t)(lane ^ (g << 2)));
                    asm volatile("ld.shared.b32 %0, [%1];"
                                 : "=r"(bfrag[nsub][vi]) : "r"(addr));
                }
#pragma unroll
            for (int msub = 0; msub < 2; ++msub)
#pragma unroll
                for (int nsub = 0; nsub < 4; ++nsub)
                    mma_tf32(acc[msub][nsub][0], acc[msub][nsub][1],
                             acc[msub][nsub][2], acc[msub][nsub][3],
                             afrag[msub][0], afrag[msub][1],
                             afrag[msub][2], afrag[msub][3],
                             bfrag[nsub][0], bfrag[nsub][1]);
        }

        // issue stage s+3
        if (s + 3 < NSTAGE) {
            const uint32_t nb = sbase0 + (uint32_t)((s + 3) & 3) * STAGE_BYTES;
            const int ko = (s + 3) * BK;
#pragma unroll
            for (int i = 0; i < 2; ++i)
                cpa16(nb + offA[i], Ag + (size_t)(32 * i) * IN_SIZE + ko);
#pragma unroll
            for (int i = 0; i < 4; ++i)
                cpa16(nb + offB[i], Bg + (size_t)(32 * i) * IN_SIZE + ko);
        }
        cpa_commit();
        __syncthreads();
    }

    // ---- epilogue: bias + relu, float2 stores
#pragma unroll
    for (int msub = 0; msub < 2; ++msub) {
        const int m = m0 + warpm * 32 + msub * 16 + (lane >> 2);
#pragma unroll
        for (int nsub = 0; nsub < 4; ++nsub) {
            const int n = n0 + warpn * 32 + nsub * 8 + (lane & 3) * 2;
            float2 bv = *reinterpret_cast<const float2*>(bias + n);
            float2 o0, o1;
            o0.x = fmaxf(acc[msub][nsub][0] + bv.x, 0.f);
            o0.y = fmaxf(acc[msub][nsub][1] + bv.y, 0.f);
            o1.x = fmaxf(acc[msub][nsub][2] + bv.x, 0.f);
            o1.y = fmaxf(acc[msub][nsub][3] + bv.y, 0.f);
            *reinterpret_cast<float2*>(out + (size_t)m * OUT_SIZE + n)       = o0;
            *reinterpret_cast<float2*>(out + (size_t)(m + 8) * OUT_SIZE + n) = o1;
        }
    }
}

// ---------------------------------------------------------------------------
// kernel_launch
// ---------------------------------------------------------------------------
extern "C" void kernel_launch(void* const* d_in, const int* in_sizes, int n_in,
                              void* d_out, int out_size) {
    const float* X    = (const float*)d_in[0];
    const void*  idx  = d_in[1];
    const float* val  = (const float*)d_in[2];
    const float* bias = (const float*)d_in[3];
    float*       out  = (float*)d_out;

    const int nnz = in_sizes[2];

    zero_w_kernel<<<(int)(((size_t)IN_SIZE * OUT_SIZE / 4) / 256), 256>>>();
    detect_idx_kernel<<<1, 32>>>((const uint32_t*)idx);
    scatter_kernel<<<(nnz + 255) / 256, 256>>>(idx, val, nnz);
    cvt_w_kernel<<<(int)(((size_t)IN_SIZE * OUT_SIZE / 4) / 256), 256>>>();
    cvt_x_kernel<<<(int)(((size_t)BATCH * IN_SIZE / 4) / 256), 256>>>(X);

    cudaFuncSetAttribute(gemm_tf32_mma,
                         cudaFuncAttributeMaxDynamicSharedMemorySize, SMEM_BYTES);
    dim3 grid(OUT_SIZE / 128, BATCH / 64);   // (32, 4) = 128 CTAs
    gemm_tf32_mma<<<grid, 256, SMEM_BYTES>>>(bias, out);
}

// round 5
// speedup vs baseline: 1.5623x; 1.5623x over previous
#include <cuda_runtime.h>
#include <stdint.h>

#define IN_SIZE  4096
#define OUT_SIZE 4096
#define BATCH    256

#define BK      32
#define NSTAGE  (IN_SIZE / BK)     // 128
#define STAGES  4
#define A_BYTES 8192               // 64 rows x 128B
#define B_BYTES 16384              // 128 rows x 128B
#define STAGE_BYTES (A_BYTES + B_BYTES)
#define SMEM_BYTES (STAGES * STAGE_BYTES)

// Transposed dense weight g_Wt[out][in]; entries are tf32-rounded values
// (scatter adds pre-rounded vals; duplicate sums get HW-truncated by the MMA).
__device__ float    g_Wt[(size_t)IN_SIZE * OUT_SIZE];
__device__ uint32_t g_Xt[(size_t)BATCH * IN_SIZE];     // X as tf32 (RNA) bits
__device__ int      g_idx_is64;

// ---------------------------------------------------------------------------
// helpers
// ---------------------------------------------------------------------------
__device__ __forceinline__ uint32_t f2tf32(float f) {
    uint32_t u;
    asm("cvt.rna.tf32.f32 %0, %1;" : "=r"(u) : "f"(f));
    return u;
}
__device__ __forceinline__ uint32_t smem_u32(const void* p) {
    uint32_t a;
    asm("{ .reg .u64 t; cvta.to.shared.u64 t, %1; cvt.u32.u64 %0, t; }"
        : "=r"(a) : "l"(p));
    return a;
}
__device__ __forceinline__ void cpa16(uint32_t s, const void* g) {
    asm volatile("cp.async.cg.shared.global [%0], [%1], 16;" :: "r"(s), "l"(g));
}
__device__ __forceinline__ void cpa_commit() {
    asm volatile("cp.async.commit_group;" ::: "memory");
}
template <int N>
__device__ __forceinline__ void cpa_wait() {
    asm volatile("cp.async.wait_group %0;" :: "n"(N) : "memory");
}
__device__ __forceinline__ void ldsm_x4(uint32_t& r0, uint32_t& r1,
                                        uint32_t& r2, uint32_t& r3, uint32_t a) {
    asm volatile("ldmatrix.sync.aligned.m8n8.x4.shared.b16 {%0,%1,%2,%3}, [%4];"
                 : "=r"(r0), "=r"(r1), "=r"(r2), "=r"(r3) : "r"(a));
}
__device__ __forceinline__ void ldsm_x2(uint32_t& r0, uint32_t& r1, uint32_t a) {
    asm volatile("ldmatrix.sync.aligned.m8n8.x2.shared.b16 {%0,%1}, [%2];"
                 : "=r"(r0), "=r"(r1) : "r"(a));
}
__device__ __forceinline__ void mma_tf32(float& d0, float& d1, float& d2, float& d3,
                                         uint32_t a0, uint32_t a1, uint32_t a2, uint32_t a3,
                                         uint32_t b0, uint32_t b1) {
    asm volatile(
        "mma.sync.aligned.m16n8k8.row.col.f32.tf32.tf32.f32 "
        "{%0,%1,%2,%3}, {%4,%5,%6,%7}, {%8,%9}, {%0,%1,%2,%3};"
        : "+f"(d0), "+f"(d1), "+f"(d2), "+f"(d3)
        : "r"(a0), "r"(a1), "r"(a2), "r"(a3), "r"(b0), "r"(b1));
}

// ---------------------------------------------------------------------------
// Zero Wt
// ---------------------------------------------------------------------------
__global__ void zero_w_kernel() {
    size_t i = (size_t)blockIdx.x * blockDim.x + threadIdx.x;
    reinterpret_cast<float4*>(g_Wt)[i] = make_float4(0.f, 0.f, 0.f, 0.f);
}

// ---------------------------------------------------------------------------
// Detect idx dtype: indices < 4096 => int64 layout has all odd u32 words zero.
// ---------------------------------------------------------------------------
__global__ void detect_idx_kernel(const uint32_t* __restrict__ idx_words) {
    if (threadIdx.x == 0) {
        uint32_t acc = 0;
#pragma unroll
        for (int i = 0; i < 64; ++i) acc |= idx_words[2 * i + 1];
        g_idx_is64 = (acc == 0u) ? 1 : 0;
    }
}

// ---------------------------------------------------------------------------
// Scatter: g_Wt[col][row] += tf32(val). Single-hit cells end up exact tf32.
// ---------------------------------------------------------------------------
__global__ void scatter_kernel(const void* __restrict__ idx,
                               const float* __restrict__ val,
                               int nnz) {
    int i = blockIdx.x * blockDim.x + threadIdx.x;
    if (i >= nnz) return;
    int row, col;
    if (g_idx_is64) {
        longlong2 p = reinterpret_cast<const longlong2*>(idx)[i];
        row = (int)p.x;
        col = (int)p.y;
    } else {
        int2 p = reinterpret_cast<const int2*>(idx)[i];
        row = p.x;
        col = p.y;
    }
    float v = __uint_as_float(f2tf32(val[i]));
    atomicAdd(&g_Wt[(size_t)col * IN_SIZE + row], v);
}

// ---------------------------------------------------------------------------
// X -> tf32 bits (RNA)
// ---------------------------------------------------------------------------
__global__ void cvt_x_kernel(const float* __restrict__ X) {
    size_t i = (size_t)blockIdx.x * blockDim.x + threadIdx.x;
    float4 v = reinterpret_cast<const float4*>(X)[i];
    uint4 u = make_uint4(f2tf32(v.x), f2tf32(v.y), f2tf32(v.z), f2tf32(v.w));
    reinterpret_cast<uint4*>(g_Xt)[i] = u;
}

// ---------------------------------------------------------------------------
// tf32 mma.sync GEMM v3 (ldmatrix): out = relu(X @ Wt^T + bias)
//
// CTA 64(M) x 128(N), 512 threads = 16 warps as 4(m) x 4(n); warp tile 16x32.
// K staged 32/iter, 4-stage cp.async pipeline (96 KB smem), 1 sync per stage.
//
// SMEM per stage: A 64x128B then B 128x128B, row-major, chunk swizzle:
//   byte_off(row, kchunk) = row*128 + ((kchunk ^ (row&7)) << 4)
// 16B global chunks map to aligned 16B smem quads (cp.async-compatible) and
// ldmatrix reads are conflict-free (8 rows hit 8 distinct 16B banks).
// ---------------------------------------------------------------------------
__global__ __launch_bounds__(512, 1)
void gemm_tf32_mma(const float* __restrict__ bias, float* __restrict__ out) {
    extern __shared__ uint32_t smu[];
    const uint32_t sbase0 = smem_u32(smu);

    const int tid   = threadIdx.x;
    const int lane  = tid & 31;
    const int wid   = tid >> 5;
    const int warpm = wid & 3;          // 0..3 -> 16 rows each
    const int warpn = wid >> 2;         // 0..3 -> 32 cols each
    const int m0 = blockIdx.y * 64;
    const int n0 = blockIdx.x * 128;

    // staging map: thread covers chunk sj of A row srow and B rows {srow, srow+64}
    const int srow = tid >> 3;          // 0..63
    const int sj   = tid & 7;

    const uint32_t* Ag = g_Xt + (size_t)(m0 + srow) * IN_SIZE + sj * 4;
    const uint32_t* Bg = reinterpret_cast<const uint32_t*>(g_Wt) +
                         (size_t)(n0 + srow) * IN_SIZE + sj * 4;

    const uint32_t offA  = (uint32_t)(srow * 128 + ((sj ^ (srow & 7)) << 4));
    const uint32_t offB0 = A_BYTES + offA;                         // row srow
    const uint32_t offB1 = A_BYTES +
        (uint32_t)((srow + 64) * 128 + ((sj ^ (srow & 7)) << 4));  // row srow+64

    // ldmatrix lane-address components
    const int rA  = warpm * 16 + ((lane >> 3) & 1) * 8 + (lane & 7);
    const int qa  = lane >> 4;                  // 0..1 (k-quad select for A)
    const int qb  = (lane >> 3) & 1;            // 0..1 (k-quad select for B)
    const uint32_t rAbase = (uint32_t)(rA * 128);
    const int rA7 = rA & 7;
    int rB[4], rB7[4];
#pragma unroll
    for (int nsub = 0; nsub < 4; ++nsub) {
        rB[nsub]  = warpn * 32 + nsub * 8 + (lane & 7);
        rB7[nsub] = rB[nsub] & 7;
    }

    float acc[4][4];
#pragma unroll
    for (int b = 0; b < 4; ++b)
#pragma unroll
        for (int d = 0; d < 4; ++d) acc[b][d] = 0.f;

    // ---- prologue: issue stages 0..2
#pragma unroll
    for (int ps = 0; ps < 3; ++ps) {
        const uint32_t sb = sbase0 + (uint32_t)ps * STAGE_BYTES;
        cpa16(sb + offA,  Ag + ps * BK);
        cpa16(sb + offB0, Bg + ps * BK);
        cpa16(sb + offB1, Bg + (size_t)64 * IN_SIZE + ps * BK);
        cpa_commit();
    }

    for (int s = 0; s < NSTAGE; ++s) {
        cpa_wait<2>();
        __syncthreads();

        // issue stage s+3 into buffer (s+3)&3 == (s-1)&3 (consumed last iter)
        if (s + 3 < NSTAGE) {
            const uint32_t nb = sbase0 + (uint32_t)((s + 3) & 3) * STAGE_BYTES;
            const int ko = (s + 3) * BK;
            cpa16(nb + offA,  Ag + ko);
            cpa16(nb + offB0, Bg + ko);
            cpa16(nb + offB1, Bg + (size_t)64 * IN_SIZE + ko);
        }
        cpa_commit();

        const uint32_t sb = sbase0 + (uint32_t)(s & 3) * STAGE_BYTES;
#pragma unroll
        for (int ks = 0; ks < 4; ++ks) {
            uint32_t a0, a1, a2, a3;
            ldsm_x4(a0, a1, a2, a3,
                    sb + rAbase + (uint32_t)((((ks * 2 + qa) ^ rA7)) << 4));
            uint32_t bf[4][2];
#pragma unroll
            for (int nsub = 0; nsub < 4; ++nsub)
                ldsm_x2(bf[nsub][0], bf[nsub][1],
                        sb + A_BYTES + (uint32_t)(rB[nsub] * 128) +
                        (uint32_t)((((ks * 2 + qb) ^ rB7[nsub])) << 4));
#pragma unroll
            for (int nsub = 0; nsub < 4; ++nsub)
                mma_tf32(acc[nsub][0], acc[nsub][1], acc[nsub][2], acc[nsub][3],
                         a0, a1, a2, a3, bf[nsub][0], bf[nsub][1]);
        }
        __syncthreads();
    }

    // ---- epilogue: bias + relu, float2 stores
    const int m = m0 + warpm * 16 + (lane >> 2);
#pragma unroll
    for (int nsub = 0; nsub < 4; ++nsub) {
        const int n = n0 + warpn * 32 + nsub * 8 + (lane & 3) * 2;
        float2 bv = *reinterpret_cast<const float2*>(bias + n);
        float2 o0, o1;
        o0.x = fmaxf(acc[nsub][0] + bv.x, 0.f);
        o0.y = fmaxf(acc[nsub][1] + bv.y, 0.f);
        o1.x = fmaxf(acc[nsub][2] + bv.x, 0.f);
        o1.y = fmaxf(acc[nsub][3] + bv.y, 0.f);
        *reinterpret_cast<float2*>(out + (size_t)m * OUT_SIZE + n)       = o0;
        *reinterpret_cast<float2*>(out + (size_t)(m + 8) * OUT_SIZE + n) = o1;
    }
}

// ---------------------------------------------------------------------------
// kernel_launch
// ---------------------------------------------------------------------------
extern "C" void kernel_launch(void* const* d_in, const int* in_sizes, int n_in,
                              void* d_out, int out_size) {
    const float* X    = (const float*)d_in[0];
    const void*  idx  = d_in[1];
    const float* val  = (const float*)d_in[2];
    const float* bias = (const float*)d_in[3];
    float*       out  = (float*)d_out;

    const int nnz = in_sizes[2];

    zero_w_kernel<<<(int)(((size_t)IN_SIZE * OUT_SIZE / 4) / 256), 256>>>();
    detect_idx_kernel<<<1, 32>>>((const uint32_t*)idx);
    scatter_kernel<<<(nnz + 255) / 256, 256>>>(idx, val, nnz);
    cvt_x_kernel<<<(int)(((size_t)BATCH * IN_SIZE / 4) / 256), 256>>>(X);

    cudaFuncSetAttribute(gemm_tf32_mma,
                         cudaFuncAttributeMaxDynamicSharedMemorySize, SMEM_BYTES);
    dim3 grid(OUT_SIZE / 128, BATCH / 64);   // (32, 4) = 128 CTAs
    gemm_tf32_mma<<<grid, 512, SMEM_BYTES>>>(bias, out);
}

// round 6
// speedup vs baseline: 1.6343x; 1.0461x over previous
#include <cuda_runtime.h>
#include <stdint.h>

#define IN_SIZE  4096
#define OUT_SIZE 4096
#define BATCH    256

#define BK      32
#define NSTAGE  (IN_SIZE / BK)     // 128
#define STAGES  4
#define A_BYTES 8192               // 64 rows x 128B
#define B_BYTES 16384              // 128 rows x 128B
#define STAGE_BYTES (A_BYTES + B_BYTES)
#define SMEM_BYTES (STAGES * STAGE_BYTES)

// Transposed dense weight g_Wt[out][in]; entries are tf32-rounded values.
__device__ float    g_Wt[(size_t)IN_SIZE * OUT_SIZE];
__device__ uint32_t g_Xt[(size_t)BATCH * IN_SIZE];     // X as tf32 (RNA) bits
__device__ int      g_idx_is64;

// ---------------------------------------------------------------------------
// helpers
// ---------------------------------------------------------------------------
__device__ __forceinline__ uint32_t f2tf32(float f) {
    uint32_t u;
    asm("cvt.rna.tf32.f32 %0, %1;" : "=r"(u) : "f"(f));
    return u;
}
__device__ __forceinline__ uint32_t smem_u32(const void* p) {
    uint32_t a;
    asm("{ .reg .u64 t; cvta.to.shared.u64 t, %1; cvt.u32.u64 %0, t; }"
        : "=r"(a) : "l"(p));
    return a;
}
__device__ __forceinline__ void cpa16(uint32_t s, const void* g) {
    asm volatile("cp.async.cg.shared.global [%0], [%1], 16;" :: "r"(s), "l"(g));
}
__device__ __forceinline__ void cpa_commit() {
    asm volatile("cp.async.commit_group;" ::: "memory");
}
template <int N>
__device__ __forceinline__ void cpa_wait() {
    asm volatile("cp.async.wait_group %0;" :: "n"(N) : "memory");
}
__device__ __forceinline__ void ldsm_x4(uint32_t& r0, uint32_t& r1,
                                        uint32_t& r2, uint32_t& r3, uint32_t a) {
    asm volatile("ldmatrix.sync.aligned.m8n8.x4.shared.b16 {%0,%1,%2,%3}, [%4];"
                 : "=r"(r0), "=r"(r1), "=r"(r2), "=r"(r3) : "r"(a));
}
__device__ __forceinline__ void mma_tf32(float& d0, float& d1, float& d2, float& d3,
                                         uint32_t a0, uint32_t a1, uint32_t a2, uint32_t a3,
                                         uint32_t b0, uint32_t b1) {
    asm volatile(
        "mma.sync.aligned.m16n8k8.row.col.f32.tf32.tf32.f32 "
        "{%0,%1,%2,%3}, {%4,%5,%6,%7}, {%8,%9}, {%0,%1,%2,%3};"
        : "+f"(d0), "+f"(d1), "+f"(d2), "+f"(d3)
        : "r"(a0), "r"(a1), "r"(a2), "r"(a3), "r"(b0), "r"(b1));
}

// ---------------------------------------------------------------------------
// Zero Wt + fused idx dtype detection (block 0).
// Indices < 4096 => int64 layout has all odd u32 words zero.
// ---------------------------------------------------------------------------
__global__ void zero_w_detect_kernel(const uint32_t* __restrict__ idx_words) {
    size_t i = (size_t)blockIdx.x * blockDim.x + threadIdx.x;
    reinterpret_cast<float4*>(g_Wt)[i] = make_float4(0.f, 0.f, 0.f, 0.f);
    if (blockIdx.x == 0 && threadIdx.x == 0) {
        uint32_t acc = 0;
#pragma unroll
        for (int j = 0; j < 64; ++j) acc |= idx_words[2 * j + 1];
        g_idx_is64 = (acc == 0u) ? 1 : 0;
    }
}

// ---------------------------------------------------------------------------
// Scatter: g_Wt[col][row] += tf32(val). Duplicates accumulate.
// ---------------------------------------------------------------------------
__global__ void scatter_kernel(const void* __restrict__ idx,
                               const float* __restrict__ val,
                               int nnz) {
    int i = blockIdx.x * blockDim.x + threadIdx.x;
    if (i >= nnz) return;
    int row, col;
    if (g_idx_is64) {
        longlong2 p = reinterpret_cast<const longlong2*>(idx)[i];
        row = (int)p.x;
        col = (int)p.y;
    } else {
        int2 p = reinterpret_cast<const int2*>(idx)[i];
        row = p.x;
        col = p.y;
    }
    float v = __uint_as_float(f2tf32(val[i]));
    atomicAdd(&g_Wt[(size_t)col * IN_SIZE + row], v);
}

// ---------------------------------------------------------------------------
// X -> tf32 bits (RNA)
// ---------------------------------------------------------------------------
__global__ void cvt_x_kernel(const float* __restrict__ X) {
    size_t i = (size_t)blockIdx.x * blockDim.x + threadIdx.x;
    float4 v = reinterpret_cast<const float4*>(X)[i];
    uint4 u = make_uint4(f2tf32(v.x), f2tf32(v.y), f2tf32(v.z), f2tf32(v.w));
    reinterpret_cast<uint4*>(g_Xt)[i] = u;
}

// ---------------------------------------------------------------------------
// tf32 mma.sync GEMM v4: out = relu(X @ Wt^T + bias)
//
// CTA 64(M) x 128(N), 512 threads = 16 warps (4m x 4n), warp tile 16x32.
// K staged 32/iter, 4-stage cp.async pipeline, ONE sync per stage.
// Per warp per ks: 1 ldsm_x4 (A) + 2 ldsm_x4 (B nsub-pairs) + 4 HMMA.
//
// SMEM per stage: A 64x128B then B 128x128B, row-major, chunk swizzle:
//   byte_off(row, kchunk) = row*128 + ((kchunk ^ (row&7)) << 4)
// ---------------------------------------------------------------------------
__global__ __launch_bounds__(512, 1)
void gemm_tf32_mma(const float* __restrict__ bias, float* __restrict__ out) {
    extern __shared__ uint32_t smu[];
    const uint32_t sbase0 = smem_u32(smu);

    const int tid   = threadIdx.x;
    const int lane  = tid & 31;
    const int wid   = tid >> 5;
    const int warpm = wid & 3;          // 0..3 -> 16 rows each
    const int warpn = wid >> 2;         // 0..3 -> 32 cols each
    const int m0 = blockIdx.y * 64;
    const int n0 = blockIdx.x * 128;

    // staging: thread covers chunk sj of A row srow and B rows {srow, srow+64}
    const int srow = tid >> 3;          // 0..63
    const int sj   = tid & 7;

    const uint32_t* Ag = g_Xt + (size_t)(m0 + srow) * IN_SIZE + sj * 4;
    const uint32_t* Bg = reinterpret_cast<const uint32_t*>(g_Wt) +
                         (size_t)(n0 + srow) * IN_SIZE + sj * 4;

    const uint32_t offA  = (uint32_t)(srow * 128 + ((sj ^ (srow & 7)) << 4));
    const uint32_t offB0 = A_BYTES + offA;
    const uint32_t offB1 = A_BYTES +
        (uint32_t)((srow + 64) * 128 + ((sj ^ (srow & 7)) << 4));

    // ldmatrix lane-address components
    const int l7 = lane & 7;
    // A x4: mats 0/1 = rows (8-groups), mats 2/3 = k-quad 1
    const int rA  = warpm * 16 + ((lane >> 3) & 1) * 8 + l7;
    const int qa  = lane >> 4;                  // k-quad select (mats 2,3)
    const uint32_t rAbase = (uint32_t)(rA * 128);
    // B x4 for nsub pair p: mat = lane>>3: {pair row-group, kq} =
    //   m0:(ns,q0) m1:(ns,q1) m2:(ns+1,q0) m3:(ns+1,q1)
    const int qb = (lane >> 3) & 1;             // k-quad select
    int rBp[2];
#pragma unroll
    for (int p = 0; p < 2; ++p)
        rBp[p] = warpn * 32 + p * 16 + ((lane >> 4) << 3) + l7;

    float acc[4][4];
#pragma unroll
    for (int b = 0; b < 4; ++b)
#pragma unroll
        for (int d = 0; d < 4; ++d) acc[b][d] = 0.f;

    // ---- prologue: issue stages 0..2
#pragma unroll
    for (int ps = 0; ps < 3; ++ps) {
        const uint32_t sb = sbase0 + (uint32_t)ps * STAGE_BYTES;
        cpa16(sb + offA,  Ag + ps * BK);
        cpa16(sb + offB0, Bg + ps * BK);
        cpa16(sb + offB1, Bg + (size_t)64 * IN_SIZE + ps * BK);
        cpa_commit();
    }

    for (int s = 0; s < NSTAGE; ++s) {
        cpa_wait<2>();
        __syncthreads();   // all warps: stage s visible AND stage s-1 compute done

        // issue stage s+3 into buffer (s-1)&3 (fully consumed last iteration)
        if (s + 3 < NSTAGE) {
            const uint32_t nb = sbase0 + (uint32_t)((s + 3) & 3) * STAGE_BYTES;
            const int ko = (s + 3) * BK;
            cpa16(nb + offA,  Ag + ko);
            cpa16(nb + offB0, Bg + ko);
            cpa16(nb + offB1, Bg + (size_t)64 * IN_SIZE + ko);
        }
        cpa_commit();

        const uint32_t sb = sbase0 + (uint32_t)(s & 3) * STAGE_BYTES;
#pragma unroll
        for (int ks = 0; ks < 4; ++ks) {
            uint32_t a0, a1, a2, a3;
            ldsm_x4(a0, a1, a2, a3,
                    sb + rAbase + (uint32_t)(((ks * 2 + qa) ^ l7) << 4));
            uint32_t bf[4][2];
#pragma unroll
            for (int p = 0; p < 2; ++p)
                ldsm_x4(bf[2 * p][0], bf[2 * p][1], bf[2 * p + 1][0], bf[2 * p + 1][1],
                        sb + A_BYTES + (uint32_t)(rBp[p] * 128) +
                        (uint32_t)(((ks * 2 + qb) ^ l7) << 4));
#pragma unroll
            for (int nsub = 0; nsub < 4; ++nsub)
                mma_tf32(acc[nsub][0], acc[nsub][1], acc[nsub][2], acc[nsub][3],
                         a0, a1, a2, a3, bf[nsub][0], bf[nsub][1]);
        }
    }

    // ---- epilogue: bias + relu, float2 stores
    const int m = m0 + warpm * 16 + (lane >> 2);
#pragma unroll
    for (int nsub = 0; nsub < 4; ++nsub) {
        const int n = n0 + warpn * 32 + nsub * 8 + (lane & 3) * 2;
        float2 bv = *reinterpret_cast<const float2*>(bias + n);
        float2 o0, o1;
        o0.x = fmaxf(acc[nsub][0] + bv.x, 0.f);
        o0.y = fmaxf(acc[nsub][1] + bv.y, 0.f);
        o1.x = fmaxf(acc[nsub][2] + bv.x, 0.f);
        o1.y = fmaxf(acc[nsub][3] + bv.y, 0.f);
        *reinterpret_cast<float2*>(out + (size_t)m * OUT_SIZE + n)       = o0;
        *reinterpret_cast<float2*>(out + (size_t)(m + 8) * OUT_SIZE + n) = o1;
    }
}

// ---------------------------------------------------------------------------
// kernel_launch
// ---------------------------------------------------------------------------
extern "C" void kernel_launch(void* const* d_in, const int* in_sizes, int n_in,
                              void* d_out, int out_size) {
    const float* X    = (const float*)d_in[0];
    const void*  idx  = d_in[1];
    const float* val  = (const float*)d_in[2];
    const float* bias = (const float*)d_in[3];
    float*       out  = (float*)d_out;

    const int nnz = in_sizes[2];

    zero_w_detect_kernel<<<(int)(((size_t)IN_SIZE * OUT_SIZE / 4) / 256), 256>>>(
        (const uint32_t*)idx);
    scatter_kernel<<<(nnz + 255) / 256, 256>>>(idx, val, nnz);
    cvt_x_kernel<<<(int)(((size_t)BATCH * IN_SIZE / 4) / 256), 256>>>(X);

    cudaFuncSetAttribute(gemm_tf32_mma,
                         cudaFuncAttributeMaxDynamicSharedMemorySize, SMEM_BYTES);
    dim3 grid(OUT_SIZE / 128, BATCH / 64);   // (32, 4) = 128 CTAs
    gemm_tf32_mma<<<grid, 512, SMEM_BYTES>>>(bias, out);
}

// round 7
// speedup vs baseline: 1.7388x; 1.0639x over previous
#include <cuda_runtime.h>
#include <stdint.h>

#define IN_SIZE  4096
#define OUT_SIZE 4096
#define BATCH    256

#define BK      32
#define NSTAGE  (IN_SIZE / BK)     // 128
#define STAGES  4
#define A_BYTES 8192               // 64 rows x 128B
#define B_BYTES 16384              // 128 rows x 128B
#define STAGE_BYTES (A_BYTES + B_BYTES)
#define SMEM_BYTES (STAGES * STAGE_BYTES)

// Transposed dense weight g_Wt[out][in]; entries are tf32-rounded values.
__device__ float    g_Wt[(size_t)IN_SIZE * OUT_SIZE];
__device__ uint32_t g_Xt[(size_t)BATCH * IN_SIZE];     // X as tf32 (RNA) bits
__device__ int      g_idx_is64;

// ---------------------------------------------------------------------------
// helpers
// ---------------------------------------------------------------------------
__device__ __forceinline__ uint32_t f2tf32(float f) {
    uint32_t u;
    asm("cvt.rna.tf32.f32 %0, %1;" : "=r"(u) : "f"(f));
    return u;
}
__device__ __forceinline__ uint32_t smem_u32(const void* p) {
    uint32_t a;
    asm("{ .reg .u64 t; cvta.to.shared.u64 t, %1; cvt.u32.u64 %0, t; }"
        : "=r"(a) : "l"(p));
    return a;
}
__device__ __forceinline__ void cpa16(uint32_t s, const void* g) {
    asm volatile("cp.async.cg.shared.global [%0], [%1], 16;" :: "r"(s), "l"(g));
}
__device__ __forceinline__ void cpa_commit() {
    asm volatile("cp.async.commit_group;" ::: "memory");
}
template <int N>
__device__ __forceinline__ void cpa_wait() {
    asm volatile("cp.async.wait_group %0;" :: "n"(N) : "memory");
}
__device__ __forceinline__ void ldsm_x4(uint32_t& r0, uint32_t& r1,
                                        uint32_t& r2, uint32_t& r3, uint32_t a) {
    asm volatile("ldmatrix.sync.aligned.m8n8.x4.shared.b16 {%0,%1,%2,%3}, [%4];"
                 : "=r"(r0), "=r"(r1), "=r"(r2), "=r"(r3) : "r"(a));
}
__device__ __forceinline__ void mma_tf32(float& d0, float& d1, float& d2, float& d3,
                                         uint32_t a0, uint32_t a1, uint32_t a2, uint32_t a3,
                                         uint32_t b0, uint32_t b1) {
    asm volatile(
        "mma.sync.aligned.m16n8k8.row.col.f32.tf32.tf32.f32 "
        "{%0,%1,%2,%3}, {%4,%5,%6,%7}, {%8,%9}, {%0,%1,%2,%3};"
        : "+f"(d0), "+f"(d1), "+f"(d2), "+f"(d3)
        : "r"(a0), "r"(a1), "r"(a2), "r"(a3), "r"(b0), "r"(b1));
}

// ---------------------------------------------------------------------------
// Zero Wt + fused idx dtype detection (block 0).
// ---------------------------------------------------------------------------
__global__ void zero_w_detect_kernel(const uint32_t* __restrict__ idx_words) {
    size_t i = (size_t)blockIdx.x * blockDim.x + threadIdx.x;
    reinterpret_cast<float4*>(g_Wt)[i] = make_float4(0.f, 0.f, 0.f, 0.f);
    if (blockIdx.x == 0 && threadIdx.x == 0) {
        uint32_t acc = 0;
#pragma unroll
        for (int j = 0; j < 64; ++j) acc |= idx_words[2 * j + 1];
        g_idx_is64 = (acc == 0u) ? 1 : 0;
    }
}

// ---------------------------------------------------------------------------
// Scatter: g_Wt[col][row] += tf32(val). Duplicates accumulate.
// ---------------------------------------------------------------------------
__global__ void scatter_kernel(const void* __restrict__ idx,
                               const float* __restrict__ val,
                               int nnz) {
    int i = blockIdx.x * blockDim.x + threadIdx.x;
    if (i >= nnz) return;
    int row, col;
    if (g_idx_is64) {
        longlong2 p = reinterpret_cast<const longlong2*>(idx)[i];
        row = (int)p.x;
        col = (int)p.y;
    } else {
        int2 p = reinterpret_cast<const int2*>(idx)[i];
        row = p.x;
        col = p.y;
    }
    float v = __uint_as_float(f2tf32(val[i]));
    atomicAdd(&g_Wt[(size_t)col * IN_SIZE + row], v);
}

// ---------------------------------------------------------------------------
// X -> tf32 bits (RNA)
// ---------------------------------------------------------------------------
__global__ void cvt_x_kernel(const float* __restrict__ X) {
    size_t i = (size_t)blockIdx.x * blockDim.x + threadIdx.x;
    float4 v = reinterpret_cast<const float4*>(X)[i];
    uint4 u = make_uint4(f2tf32(v.x), f2tf32(v.y), f2tf32(v.z), f2tf32(v.w));
    reinterpret_cast<uint4*>(g_Xt)[i] = u;
}

// ---------------------------------------------------------------------------
// tf32 mma.sync GEMM v5: out = relu(X @ Wt^T + bias)
//
// CTA 64(M) x 128(N), 128 threads = 4 warps (2m x 2n), warp tile 32x64.
// Per warp per ks: 2 ldsm_x4 (A msubs) + 4 ldsm_x4 (B nsub-pairs) + 16 HMMA.
// SMEM reads/CTA/stage = 48 KB (vs 96 KB at warp tile 16x32) -> crossbar-bound
// time per stage ~576 cyc.
//
// SMEM per stage: A 64x128B then B 128x128B, row-major, chunk swizzle:
//   byte_off(row, kchunk) = row*128 + ((kchunk ^ (row&7)) << 4)
// ---------------------------------------------------------------------------
__global__ __launch_bounds__(128, 1)
void gemm_tf32_mma(const float* __restrict__ bias, float* __restrict__ out) {
    extern __shared__ uint32_t smu[];
    const uint32_t sbase0 = smem_u32(smu);

    const int tid   = threadIdx.x;
    const int lane  = tid & 31;
    const int wid   = tid >> 5;
    const int warpm = wid & 1;          // 0..1 -> 32 rows each
    const int warpn = wid >> 1;         // 0..1 -> 64 cols each
    const int m0 = blockIdx.y * 64;
    const int n0 = blockIdx.x * 128;

    // staging: srow 0..15, sj 0..7; A rows srow+16i (i<4), B rows srow+16i (i<8)
    const int srow = tid >> 3;
    const int sj   = tid & 7;

    const uint32_t* Ag = g_Xt + (size_t)(m0 + srow) * IN_SIZE + sj * 4;
    const uint32_t* Bg = reinterpret_cast<const uint32_t*>(g_Wt) +
                         (size_t)(n0 + srow) * IN_SIZE + sj * 4;

    // swizzle is invariant over +16 row steps ((srow+16i)&7 == srow&7)
    const uint32_t swz  = (uint32_t)((sj ^ (srow & 7)) << 4);
    uint32_t offA[4], offB[8];
#pragma unroll
    for (int i = 0; i < 4; ++i)
        offA[i] = (uint32_t)((srow + 16 * i) * 128) + swz;
#pragma unroll
    for (int i = 0; i < 8; ++i)
        offB[i] = A_BYTES + (uint32_t)((srow + 16 * i) * 128) + swz;

    // ldmatrix lane-address components (proven mapping from v4)
    const int l7 = lane & 7;
    const int qa = lane >> 4;            // A k-quad select (mats 2,3)
    const int qb = (lane >> 3) & 1;      // B k-quad select
    uint32_t rAbase[2];
#pragma unroll
    for (int msub = 0; msub < 2; ++msub)
        rAbase[msub] = (uint32_t)((warpm * 32 + msub * 16 +
                                   ((lane >> 3) & 1) * 8 + l7) * 128);
    uint32_t rBbase[4];
#pragma unroll
    for (int p = 0; p < 4; ++p)
        rBbase[p] = (uint32_t)((warpn * 64 + p * 16 + ((lane >> 4) << 3) + l7) * 128);

    float acc[2][8][4];
#pragma unroll
    for (int a = 0; a < 2; ++a)
#pragma unroll
        for (int b = 0; b < 8; ++b)
#pragma unroll
            for (int d = 0; d < 4; ++d) acc[a][b][d] = 0.f;

    // ---- prologue: issue stages 0..2
#pragma unroll
    for (int ps = 0; ps < 3; ++ps) {
        const uint32_t sb = sbase0 + (uint32_t)ps * STAGE_BYTES;
#pragma unroll
        for (int i = 0; i < 4; ++i)
            cpa16(sb + offA[i], Ag + (size_t)(16 * i) * IN_SIZE + ps * BK);
#pragma unroll
        for (int i = 0; i < 8; ++i)
            cpa16(sb + offB[i], Bg + (size_t)(16 * i) * IN_SIZE + ps * BK);
        cpa_commit();
    }

    for (int s = 0; s < NSTAGE; ++s) {
        cpa_wait<2>();
        __syncthreads();   // stage s visible AND stage s-1 compute done

        // issue stage s+3 into buffer (s-1)&3
        if (s + 3 < NSTAGE) {
            const uint32_t nb = sbase0 + (uint32_t)((s + 3) & 3) * STAGE_BYTES;
            const int ko = (s + 3) * BK;
#pragma unroll
            for (int i = 0; i < 4; ++i)
                cpa16(nb + offA[i], Ag + (size_t)(16 * i) * IN_SIZE + ko);
#pragma unroll
            for (int i = 0; i < 8; ++i)
                cpa16(nb + offB[i], Bg + (size_t)(16 * i) * IN_SIZE + ko);
        }
        cpa_commit();

        const uint32_t sb = sbase0 + (uint32_t)(s & 3) * STAGE_BYTES;
#pragma unroll
        for (int ks = 0; ks < 4; ++ks) {
            const uint32_t aswz = (uint32_t)(((ks * 2 + qa) ^ l7) << 4);
            const uint32_t bswz = (uint32_t)(((ks * 2 + qb) ^ l7) << 4);
            uint32_t af[2][4];
#pragma unroll
            for (int msub = 0; msub < 2; ++msub)
                ldsm_x4(af[msub][0], af[msub][1], af[msub][2], af[msub][3],
                        sb + rAbase[msub] + aswz);
            uint32_t bf[8][2];
#pragma unroll
            for (int p = 0; p < 4; ++p)
                ldsm_x4(bf[2 * p][0], bf[2 * p][1], bf[2 * p + 1][0], bf[2 * p + 1][1],
                        sb + A_BYTES + rBbase[p] + bswz);
#pragma unroll
            for (int msub = 0; msub < 2; ++msub)
#pragma unroll
                for (int nsub = 0; nsub < 8; ++nsub)
                    mma_tf32(acc[msub][nsub][0], acc[msub][nsub][1],
                             acc[msub][nsub][2], acc[msub][nsub][3],
                             af[msub][0], af[msub][1], af[msub][2], af[msub][3],
                             bf[nsub][0], bf[nsub][1]);
        }
    }

    // ---- epilogue: bias + relu, float2 stores
#pragma unroll
    for (int msub = 0; msub < 2; ++msub) {
        const int m = m0 + warpm * 32 + msub * 16 + (lane >> 2);
#pragma unroll
        for (int nsub = 0; nsub < 8; ++nsub) {
            const int n = n0 + warpn * 64 + nsub * 8 + (lane & 3) * 2;
            float2 bv = *reinterpret_cast<const float2*>(bias + n);
            float2 o0, o1;
            o0.x = fmaxf(acc[msub][nsub][0] + bv.x, 0.f);
            o0.y = fmaxf(acc[msub][nsub][1] + bv.y, 0.f);
            o1.x = fmaxf(acc[msub][nsub][2] + bv.x, 0.f);
            o1.y = fmaxf(acc[msub][nsub][3] + bv.y, 0.f);
            *reinterpret_cast<float2*>(out + (size_t)m * OUT_SIZE + n)       = o0;
            *reinterpret_cast<float2*>(out + (size_t)(m + 8) * OUT_SIZE + n) = o1;
        }
    }
}

// ---------------------------------------------------------------------------
// kernel_launch
// ---------------------------------------------------------------------------
extern "C" void kernel_launch(void* const* d_in, const int* in_sizes, int n_in,
                              void* d_out, int out_size) {
    const float* X    = (const float*)d_in[0];
    const void*  idx  = d_in[1];
    const float* val  = (const float*)d_in[2];
    const float* bias = (const float*)d_in[3];
    float*       out  = (float*)d_out;

    const int nnz = in_sizes[2];

    zero_w_detect_kernel<<<(int)(((size_t)IN_SIZE * OUT_SIZE / 4) / 256), 256>>>(
        (const uint32_t*)idx);
    scatter_kernel<<<(nnz + 255) / 256, 256>>>(idx, val, nnz);
    cvt_x_kernel<<<(int)(((size_t)BATCH * IN_SIZE / 4) / 256), 256>>>(X);

    cudaFuncSetAttribute(gemm_tf32_mma,
                         cudaFuncAttributeMaxDynamicSharedMemorySize, SMEM_BYTES);
    dim3 grid(OUT_SIZE / 128, BATCH / 64);   // (32, 4) = 128 CTAs
    gemm_tf32_mma<<<grid, 128, SMEM_BYTES>>>(bias, out);
}